// round 1
// baseline (speedup 1.0000x reference)
#include <cuda_runtime.h>
#include <math.h>

#define BSZ 2
#define SEQ 1024
#define DIM 1024
#define NH 16
#define HDIM 64
#define FFD 4096
#define NL 2
#define RNK 16
#define VOC 32000
#define MT (BSZ*SEQ)          // 2048 tokens
#define LORA_SCALE 2.0f
#define EPSV 1e-6f

// ------------------------- scratch (device globals, no allocs) -------------------------
__device__ float g_x[MT*DIM];
__device__ float g_tx[MT*DIM];
__device__ float g_h[MT*DIM];
__device__ float g_th[MT*DIM];
__device__ float g_q[MT*DIM];
__device__ float g_dq[MT*DIM];
__device__ float g_k[MT*DIM];
__device__ float g_dk[MT*DIM];
__device__ float g_v[MT*DIM];
__device__ float g_dv[MT*DIM];
__device__ float g_o[MT*DIM];
__device__ float g_do[MT*DIM];
__device__ float g_u[MT*FFD];
__device__ float g_du[MT*FFD];
__device__ float g_p[(size_t)BSZ*NH*SEQ*SEQ];
__device__ float g_dp[(size_t)BSZ*NH*SEQ*SEQ];
__device__ float g_cp[MT*RNK];
__device__ float g_ct[MT*RNK];
__device__ float g_dAq[NL*RNK*DIM];
__device__ float g_dBq[NL*DIM*RNK];
__device__ float g_dAv[NL*RNK*DIM];
__device__ float g_dBv[NL*DIM*RNK];

// ------------------------- kernels -------------------------

__global__ void k_embed(const int* __restrict__ ids, const float* __restrict__ emb,
                        float* __restrict__ x, float* __restrict__ tx)
{
    int i = blockIdx.x * 256 + threadIdx.x;          // MT*DIM total
    int tok = i >> 10;                                // DIM = 1024
    int d = i & 1023;
    x[i] = emb[(size_t)ids[tok] * DIM + d];
    tx[i] = 0.f;
}

__global__ void k_diff(const float* __restrict__ a, const float* __restrict__ b,
                       float* __restrict__ c, int n)
{
    int i = blockIdx.x * 256 + threadIdx.x;
    if (i < n) c[i] = a[i] - b[i];
}

// RMSNorm + JVP. One block per row (D=1024, 256 threads, 4 elems each).
// combine=1: H <- h + th (for the final layernorm, ALPHA=1 fused).
__global__ void k_rms(const float* __restrict__ X, const float* __restrict__ TX,
                      const float* __restrict__ g, float* __restrict__ H,
                      float* __restrict__ TH, int combine)
{
    const int row = blockIdx.x, tid = threadIdx.x;
    const float* x  = X  + (size_t)row * DIM;
    const float* tx = TX + (size_t)row * DIM;
    float xv[4], tv[4];
    float ss = 0.f, st = 0.f;
    #pragma unroll
    for (int e = 0; e < 4; e++) {
        int d = tid + e * 256;
        float a = x[d], b = tx[d];
        xv[e] = a; tv[e] = b;
        ss += a * a; st += a * b;
    }
    __shared__ float sa[8], sb[8];
    #pragma unroll
    for (int off = 16; off; off >>= 1) {
        ss += __shfl_down_sync(0xffffffffu, ss, off);
        st += __shfl_down_sync(0xffffffffu, st, off);
    }
    if ((tid & 31) == 0) { sa[tid >> 5] = ss; sb[tid >> 5] = st; }
    __syncthreads();
    if (tid < 32) {
        float a = (tid < 8) ? sa[tid] : 0.f;
        float b = (tid < 8) ? sb[tid] : 0.f;
        #pragma unroll
        for (int off = 4; off; off >>= 1) {
            a += __shfl_down_sync(0xffffffffu, a, off);
            b += __shfl_down_sync(0xffffffffu, b, off);
        }
        if (tid == 0) { sa[0] = a; sb[0] = b; }
    }
    __syncthreads();
    const float m  = sa[0] * (1.f / DIM);
    const float mm = sb[0] * (1.f / DIM);
    const float s  = 1.f / sqrtf(m + EPSV);
    const float s3mm = s * s * mm;
    #pragma unroll
    for (int e = 0; e < 4; e++) {
        int d = tid + e * 256;
        float gg = g[d];
        float hv  = gg * s * xv[e];
        float thv = gg * s * (tv[e] - xv[e] * s3mm);
        size_t idx = (size_t)row * DIM + d;
        if (combine) H[idx] = hv + thv;
        else { H[idx] = hv; TH[idx] = thv; }
    }
}

// C[M,N] (+)= A[M,K] @ B[K,N], row-major, all dims multiples of (128,64,16).
__global__ __launch_bounds__(256) void k_gemm(
    const float* __restrict__ A, const float* __restrict__ B, float* __restrict__ C,
    int M, int N, int K, int accum)
{
    __shared__ float As[16][128];
    __shared__ float Bs[16][64];
    const int tid = threadIdx.x;
    const int tx = tid & 15, ty = tid >> 4;
    const int row0 = blockIdx.y * 128;
    const int col0 = blockIdx.x * 64;

    float acc[8][4];
    #pragma unroll
    for (int i = 0; i < 8; i++)
        #pragma unroll
        for (int j = 0; j < 4; j++) acc[i][j] = 0.f;

    for (int k0 = 0; k0 < K; k0 += 16) {
        #pragma unroll
        for (int e = 0; e < 2; e++) {
            int idx = tid + e * 256;      // 512 float4 = 128x16
            int r = idx >> 2, cq = idx & 3;
            float4 va = *reinterpret_cast<const float4*>(
                &A[(size_t)(row0 + r) * K + k0 + cq * 4]);
            As[cq*4+0][r] = va.x; As[cq*4+1][r] = va.y;
            As[cq*4+2][r] = va.z; As[cq*4+3][r] = va.w;
        }
        {
            int r = tid >> 4, c = (tid & 15) * 4;   // 256 float4 = 16x64
            float4 vb = *reinterpret_cast<const float4*>(
                &B[(size_t)(k0 + r) * N + col0 + c]);
            *reinterpret_cast<float4*>(&Bs[r][c]) = vb;
        }
        __syncthreads();
        #pragma unroll
        for (int kk = 0; kk < 16; kk++) {
            float a[8], b[4];
            #pragma unroll
            for (int i = 0; i < 8; i++) a[i] = As[kk][ty * 8 + i];
            #pragma unroll
            for (int j = 0; j < 4; j++) b[j] = Bs[kk][tx * 4 + j];
            #pragma unroll
            for (int i = 0; i < 8; i++)
                #pragma unroll
                for (int j = 0; j < 4; j++)
                    acc[i][j] = fmaf(a[i], b[j], acc[i][j]);
        }
        __syncthreads();
    }
    #pragma unroll
    for (int i = 0; i < 8; i++) {
        int row = row0 + ty * 8 + i;
        #pragma unroll
        for (int j = 0; j < 4; j++) {
            size_t cidx = (size_t)row * N + col0 + tx * 4 + j;
            if (accum) C[cidx] += acc[i][j];
            else       C[cidx]  = acc[i][j];
        }
    }
}

// scores (NT, per head): out[bh,i,j] = scale * sum over pairs of A[.,i,:].B[.,j,:]
// A/B are [B,S,D] with head slice h*64. Skips fully-masked upper-tri blocks.
__global__ __launch_bounds__(256) void k_attn_nt(
    const float* __restrict__ Q1, const float* __restrict__ K1,
    const float* __restrict__ Q2, const float* __restrict__ K2,
    float* __restrict__ out, float scale, int dual)
{
    const int bh = blockIdx.z;
    const int b = bh >> 4, h = bh & 15;
    const int i0 = blockIdx.y * 64;
    const int j0 = blockIdx.x * 64;
    if (j0 > i0 + 63) return;       // fully masked -> never read
    __shared__ float Qs[64][65];
    __shared__ float Ks[64][65];
    const int tid = threadIdx.x;
    const int tx = tid & 15, ty = tid >> 4;
    const int hoff = h * 64;
    float acc[4][4];
    #pragma unroll
    for (int i = 0; i < 4; i++)
        #pragma unroll
        for (int j = 0; j < 4; j++) acc[i][j] = 0.f;

    for (int pass = 0; pass <= dual; ++pass) {
        const float* Q  = pass ? Q2 : Q1;
        const float* Kp = pass ? K2 : K1;
        #pragma unroll
        for (int e = 0; e < 4; e++) {
            int idx = tid + e * 256;          // 1024 float4 = 64x64
            int r = idx >> 4, c = (idx & 15) * 4;
            float4 vq = *reinterpret_cast<const float4*>(
                &Q[(size_t)(b * SEQ + i0 + r) * DIM + hoff + c]);
            Qs[r][c] = vq.x; Qs[r][c+1] = vq.y; Qs[r][c+2] = vq.z; Qs[r][c+3] = vq.w;
            float4 vk = *reinterpret_cast<const float4*>(
                &Kp[(size_t)(b * SEQ + j0 + r) * DIM + hoff + c]);
            Ks[r][c] = vk.x; Ks[r][c+1] = vk.y; Ks[r][c+2] = vk.z; Ks[r][c+3] = vk.w;
        }
        __syncthreads();
        #pragma unroll
        for (int kk = 0; kk < 64; kk++) {
            float a[4], bb[4];
            #pragma unroll
            for (int i = 0; i < 4; i++) a[i]  = Qs[ty * 4 + i][kk];
            #pragma unroll
            for (int j = 0; j < 4; j++) bb[j] = Ks[tx * 4 + j][kk];
            #pragma unroll
            for (int i = 0; i < 4; i++)
                #pragma unroll
                for (int j = 0; j < 4; j++)
                    acc[i][j] = fmaf(a[i], bb[j], acc[i][j]);
        }
        __syncthreads();
    }
    const size_t base = (size_t)bh * SEQ * SEQ;
    #pragma unroll
    for (int i = 0; i < 4; i++)
        #pragma unroll
        for (int j = 0; j < 4; j++)
            out[base + (size_t)(i0 + ty * 4 + i) * SEQ + j0 + tx * 4 + j] = acc[i][j] * scale;
}

// o (NN, per head): out[b,i,h,:] = sum over pairs of P[bh,i,:] @ V[b,:,h,:]
// causal: P columns beyond i0+63 are zero -> K loop truncated.
__global__ __launch_bounds__(256) void k_attn_nn(
    const float* __restrict__ P1, const float* __restrict__ V1,
    const float* __restrict__ P2, const float* __restrict__ V2,
    float* __restrict__ out, int dual)
{
    const int bh = blockIdx.z;
    const int b = bh >> 4, h = bh & 15;
    const int i0 = blockIdx.y * 64;
    __shared__ float Ps[64][65];
    __shared__ float Vs[64][65];
    const int tid = threadIdx.x;
    const int tx = tid & 15, ty = tid >> 4;
    const int hoff = h * 64;
    const int kend = i0 + 64;
    float acc[4][4];
    #pragma unroll
    for (int i = 0; i < 4; i++)
        #pragma unroll
        for (int j = 0; j < 4; j++) acc[i][j] = 0.f;

    const size_t pbase = (size_t)bh * SEQ * SEQ;
    for (int pass = 0; pass <= dual; ++pass) {
        const float* P = pass ? P2 : P1;
        const float* V = pass ? V2 : V1;
        for (int k0 = 0; k0 < kend; k0 += 64) {
            #pragma unroll
            for (int e = 0; e < 4; e++) {
                int idx = tid + e * 256;
                int r = idx >> 4, c = (idx & 15) * 4;
                float4 vp = *reinterpret_cast<const float4*>(
                    &P[pbase + (size_t)(i0 + r) * SEQ + k0 + c]);
                Ps[r][c] = vp.x; Ps[r][c+1] = vp.y; Ps[r][c+2] = vp.z; Ps[r][c+3] = vp.w;
                float4 vv = *reinterpret_cast<const float4*>(
                    &V[(size_t)(b * SEQ + k0 + r) * DIM + hoff + c]);
                Vs[r][c] = vv.x; Vs[r][c+1] = vv.y; Vs[r][c+2] = vv.z; Vs[r][c+3] = vv.w;
            }
            __syncthreads();
            #pragma unroll
            for (int kk = 0; kk < 64; kk++) {
                float a[4], bb[4];
                #pragma unroll
                for (int i = 0; i < 4; i++) a[i]  = Ps[ty * 4 + i][kk];
                #pragma unroll
                for (int j = 0; j < 4; j++) bb[j] = Vs[kk][tx * 4 + j];
                #pragma unroll
                for (int i = 0; i < 4; i++)
                    #pragma unroll
                    for (int j = 0; j < 4; j++)
                        acc[i][j] = fmaf(a[i], bb[j], acc[i][j]);
            }
            __syncthreads();
        }
    }
    #pragma unroll
    for (int i = 0; i < 4; i++)
        #pragma unroll
        for (int j = 0; j < 4; j++)
            out[(size_t)(b * SEQ + i0 + ty * 4 + i) * DIM + hoff + tx * 4 + j] = acc[i][j];
}

// Causal softmax + its JVP, in place. p <- softmax; ds <- p*(ds - <p,ds>).
__global__ void k_softmax(float* __restrict__ P, float* __restrict__ DS)
{
    const int i = blockIdx.x;
    const int bh = blockIdx.y;
    float* p  = P  + (size_t)bh * SEQ * SEQ + (size_t)i * SEQ;
    float* ds = DS + (size_t)bh * SEQ * SEQ + (size_t)i * SEQ;
    const int n = i + 1;
    const int tid = threadIdx.x;
    __shared__ float r0[8], r1[8], r2[8];

    float mx = -3.0e38f;
    for (int j = tid; j < n; j += 256) mx = fmaxf(mx, p[j]);
    #pragma unroll
    for (int off = 16; off; off >>= 1) mx = fmaxf(mx, __shfl_down_sync(0xffffffffu, mx, off));
    if ((tid & 31) == 0) r0[tid >> 5] = mx;
    __syncthreads();
    if (tid == 0) {
        float m = r0[0];
        for (int w = 1; w < 8; w++) m = fmaxf(m, r0[w]);
        r0[0] = m;
    }
    __syncthreads();
    const float m = r0[0];

    float s = 0.f, dt = 0.f;
    for (int j = tid; j < n; j += 256) {
        float e = expf(p[j] - m);
        p[j] = e;
        s += e;
        dt += e * ds[j];
    }
    #pragma unroll
    for (int off = 16; off; off >>= 1) {
        s  += __shfl_down_sync(0xffffffffu, s, off);
        dt += __shfl_down_sync(0xffffffffu, dt, off);
    }
    if ((tid & 31) == 0) { r1[tid >> 5] = s; r2[tid >> 5] = dt; }
    __syncthreads();
    if (tid == 0) {
        float a = 0.f, bq = 0.f;
        for (int w = 0; w < 8; w++) { a += r1[w]; bq += r2[w]; }
        r1[0] = a; r2[0] = bq;
    }
    __syncthreads();
    const float inv = 1.f / r1[0];
    const float pd = r2[0] * inv;
    for (int j = tid; j < SEQ; j += 256) {
        if (j < n) {
            float pv = p[j] * inv;
            p[j] = pv;
            ds[j] = pv * (ds[j] - pd);
        } else {
            p[j] = 0.f;
            ds[j] = 0.f;
        }
    }
}

// tanh-gelu + JVP, in place.
__global__ void k_gelu(float* __restrict__ U, float* __restrict__ DU)
{
    int i = blockIdx.x * 256 + threadIdx.x;
    float u = U[i], du = DU[i];
    float u2 = u * u;
    float w = 0.7978845608028654f * (u + 0.044715f * u * u2);
    float t = tanhf(w);
    float half1pt = 0.5f * (1.f + t);
    U[i] = u * half1pt;
    float dg = half1pt + 0.5f * u * (1.f - t * t) * 0.7978845608028654f * (1.f + 0.134145f * u2);
    DU[i] = du * dg;
}

// out[m,r] = X1[m,:].A1[r,:] (+ X2[m,:].A2[r,:])
__global__ void k_lora_down(const float* __restrict__ X1, const float* __restrict__ A1,
                            const float* __restrict__ X2, const float* __restrict__ A2,
                            float* __restrict__ out)
{
    __shared__ float xs[DIM];
    __shared__ float xs2[DIM];
    const int m = blockIdx.x, tid = threadIdx.x;
    #pragma unroll
    for (int e = 0; e < 4; e++) {
        int d = tid + e * 256;
        xs[d] = X1[(size_t)m * DIM + d];
        xs2[d] = X2 ? X2[(size_t)m * DIM + d] : 0.f;
    }
    __syncthreads();
    const int w = tid >> 5, lane = tid & 31;
    for (int r = w; r < RNK; r += 8) {
        float s = 0.f;
        const float* a1 = A1 + (size_t)r * DIM;
        for (int d = lane; d < DIM; d += 32) s += xs[d] * a1[d];
        if (X2) {
            const float* a2 = A2 + (size_t)r * DIM;
            for (int d = lane; d < DIM; d += 32) s += xs2[d] * a2[d];
        }
        #pragma unroll
        for (int off = 16; off; off >>= 1) s += __shfl_down_sync(0xffffffffu, s, off);
        if (lane == 0) out[m * RNK + r] = s;
    }
}

// C[m,d] += LORA_SCALE * ( C1[m,:].B1[d,:] (+ C2[m,:].B2[d,:]) ),  B* are [D,R]
__global__ void k_lora_up(float* __restrict__ C,
                          const float* __restrict__ C1, const float* __restrict__ B1,
                          const float* __restrict__ C2, const float* __restrict__ B2)
{
    const int m = blockIdx.y;
    const int d = blockIdx.x * 256 + threadIdx.x;
    __shared__ float c1[RNK], c2[RNK];
    if (threadIdx.x < RNK) {
        c1[threadIdx.x] = C1[m * RNK + threadIdx.x];
        c2[threadIdx.x] = C2 ? C2[m * RNK + threadIdx.x] : 0.f;
    }
    __syncthreads();
    float s = 0.f;
    const float* b1 = B1 + (size_t)d * RNK;
    #pragma unroll
    for (int r = 0; r < RNK; r++) s += c1[r] * b1[r];
    if (C2) {
        const float* b2 = B2 + (size_t)d * RNK;
        #pragma unroll
        for (int r = 0; r < RNK; r++) s += c2[r] * b2[r];
    }
    C[(size_t)m * DIM + d] += LORA_SCALE * s;
}

// ------------------------- host -------------------------

extern "C" void kernel_launch(void* const* d_in, const int* in_sizes, int n_in,
                              void* d_out, int out_size)
{
    (void)in_sizes; (void)n_in; (void)out_size;
    const int*   ids  = (const int*)  d_in[0];
    const float* emb  = (const float*)d_in[1];
    const float* Wq   = (const float*)d_in[2];
    const float* Wk   = (const float*)d_in[3];
    const float* Wv   = (const float*)d_in[4];
    const float* Wo   = (const float*)d_in[5];
    const float* W1   = (const float*)d_in[6];
    const float* W2   = (const float*)d_in[7];
    const float* ln1  = (const float*)d_in[8];
    const float* ln2  = (const float*)d_in[9];
    const float* lnf  = (const float*)d_in[10];
    const float* lm   = (const float*)d_in[11];
    const float* Aq0  = (const float*)d_in[12];
    const float* Bq0  = (const float*)d_in[13];
    const float* Av0  = (const float*)d_in[14];
    const float* Bv0  = (const float*)d_in[15];
    const float* Aq   = (const float*)d_in[16];
    const float* Bq   = (const float*)d_in[17];
    const float* Av   = (const float*)d_in[18];
    const float* Bv   = (const float*)d_in[19];
    float* out = (float*)d_out;

    float *x, *tx, *h, *th, *q, *dq, *k, *dk, *v, *dv, *o, *dO, *u, *du, *P, *DP;
    float *cp, *ct, *dAq, *dBq, *dAv, *dBv;
    cudaGetSymbolAddress((void**)&x,  g_x);
    cudaGetSymbolAddress((void**)&tx, g_tx);
    cudaGetSymbolAddress((void**)&h,  g_h);
    cudaGetSymbolAddress((void**)&th, g_th);
    cudaGetSymbolAddress((void**)&q,  g_q);
    cudaGetSymbolAddress((void**)&dq, g_dq);
    cudaGetSymbolAddress((void**)&k,  g_k);
    cudaGetSymbolAddress((void**)&dk, g_dk);
    cudaGetSymbolAddress((void**)&v,  g_v);
    cudaGetSymbolAddress((void**)&dv, g_dv);
    cudaGetSymbolAddress((void**)&o,  g_o);
    cudaGetSymbolAddress((void**)&dO, g_do);
    cudaGetSymbolAddress((void**)&u,  g_u);
    cudaGetSymbolAddress((void**)&du, g_du);
    cudaGetSymbolAddress((void**)&P,  g_p);
    cudaGetSymbolAddress((void**)&DP, g_dp);
    cudaGetSymbolAddress((void**)&cp, g_cp);
    cudaGetSymbolAddress((void**)&ct, g_ct);
    cudaGetSymbolAddress((void**)&dAq, g_dAq);
    cudaGetSymbolAddress((void**)&dBq, g_dBq);
    cudaGetSymbolAddress((void**)&dAv, g_dAv);
    cudaGetSymbolAddress((void**)&dBv, g_dBv);

    k_embed<<<MT*DIM/256, 256>>>(ids, emb, x, tx);
    k_diff<<<(NL*RNK*DIM+255)/256, 256>>>(Aq, Aq0, dAq, NL*RNK*DIM);
    k_diff<<<(NL*DIM*RNK+255)/256, 256>>>(Bq, Bq0, dBq, NL*DIM*RNK);
    k_diff<<<(NL*RNK*DIM+255)/256, 256>>>(Av, Av0, dAv, NL*RNK*DIM);
    k_diff<<<(NL*DIM*RNK+255)/256, 256>>>(Bv, Bv0, dBv, NL*DIM*RNK);

    const dim3 gD(DIM/64, MT/128);     // N=1024 GEMMs
    const dim3 gF(FFD/64, MT/128);     // N=4096 GEMMs
    const dim3 gV(VOC/64, MT/128);     // lm_head
    const dim3 gNT(SEQ/64, SEQ/64, BSZ*NH);
    const dim3 gNN(1, SEQ/64, BSZ*NH);
    const dim3 gLU(DIM/256, MT);

    for (int l = 0; l < NL; l++) {
        const float* wq  = Wq + (size_t)l*DIM*DIM;
        const float* wk  = Wk + (size_t)l*DIM*DIM;
        const float* wv  = Wv + (size_t)l*DIM*DIM;
        const float* wo  = Wo + (size_t)l*DIM*DIM;
        const float* w1  = W1 + (size_t)l*DIM*FFD;
        const float* w2  = W2 + (size_t)l*FFD*DIM;
        const float* aq0 = Aq0 + (size_t)l*RNK*DIM;
        const float* bq0 = Bq0 + (size_t)l*DIM*RNK;
        const float* av0 = Av0 + (size_t)l*RNK*DIM;
        const float* bv0 = Bv0 + (size_t)l*DIM*RNK;
        const float* daq = dAq + (size_t)l*RNK*DIM;
        const float* dbq = dBq + (size_t)l*DIM*RNK;
        const float* dav = dAv + (size_t)l*RNK*DIM;
        const float* dbv = dBv + (size_t)l*DIM*RNK;

        // pre-attn RMSNorm (primal h, tangent th)
        k_rms<<<MT, 256>>>(x, tx, ln1 + l*DIM, h, th, 0);

        // q / dq (+ LoRA)
        k_gemm<<<gD, 256>>>(h,  wq, q,  MT, DIM, DIM, 0);
        k_gemm<<<gD, 256>>>(th, wq, dq, MT, DIM, DIM, 0);
        k_lora_down<<<MT, 256>>>(h,  aq0, nullptr, nullptr, cp);
        k_lora_down<<<MT, 256>>>(th, aq0, h, daq, ct);
        k_lora_up<<<gLU, 256>>>(q,  cp, bq0, nullptr, nullptr);
        k_lora_up<<<gLU, 256>>>(dq, ct, bq0, cp, dbq);

        // k / dk
        k_gemm<<<gD, 256>>>(h,  wk, k,  MT, DIM, DIM, 0);
        k_gemm<<<gD, 256>>>(th, wk, dk, MT, DIM, DIM, 0);

        // v / dv (+ LoRA)
        k_gemm<<<gD, 256>>>(h,  wv, v,  MT, DIM, DIM, 0);
        k_gemm<<<gD, 256>>>(th, wv, dv, MT, DIM, DIM, 0);
        k_lora_down<<<MT, 256>>>(h,  av0, nullptr, nullptr, cp);
        k_lora_down<<<MT, 256>>>(th, av0, h, dav, ct);
        k_lora_up<<<gLU, 256>>>(v,  cp, bv0, nullptr, nullptr);
        k_lora_up<<<gLU, 256>>>(dv, ct, bv0, cp, dbv);

        // attention scores + JVP
        k_attn_nt<<<gNT, 256>>>(q,  k, nullptr, nullptr, P,  0.125f, 0);
        k_attn_nt<<<gNT, 256>>>(dq, k, q,       dk,      DP, 0.125f, 1);
        k_softmax<<<dim3(SEQ, BSZ*NH), 256>>>(P, DP);
        k_attn_nn<<<gNN, 256>>>(P,  v, nullptr, nullptr, o,  0);
        k_attn_nn<<<gNN, 256>>>(DP, v, P,       dv,      dO, 1);

        // residual: x += o@Wo, tx += do@Wo
        k_gemm<<<gD, 256>>>(o,  wo, x,  MT, DIM, DIM, 1);
        k_gemm<<<gD, 256>>>(dO, wo, tx, MT, DIM, DIM, 1);

        // FFN
        k_rms<<<MT, 256>>>(x, tx, ln2 + l*DIM, h, th, 0);
        k_gemm<<<gF, 256>>>(h,  w1, u,  MT, FFD, DIM, 0);
        k_gemm<<<gF, 256>>>(th, w1, du, MT, FFD, DIM, 0);
        k_gelu<<<MT*FFD/256, 256>>>(u, du);
        k_gemm<<<gD, 256>>>(u,  w2, x,  MT, DIM, FFD, 1);
        k_gemm<<<gD, 256>>>(du, w2, tx, MT, DIM, FFD, 1);
    }

    // final norm: z = rms(x) + rms_jvp(x,tx)  (ALPHA=1), then lm_head
    k_rms<<<MT, 256>>>(x, tx, lnf, h, nullptr, 1);
    k_gemm<<<gV, 256>>>(h, lm, out, MT, VOC, DIM, 0);
}

// round 2
// speedup vs baseline: 2.0341x; 2.0341x over previous
#include <cuda_runtime.h>
#include <math.h>
#include <stdint.h>

#define BSZ 2
#define SEQ 1024
#define DIM 1024
#define NH 16
#define HDIM 64
#define FFD 4096
#define NL 2
#define RNK 16
#define VOC 32000
#define MT (BSZ*SEQ)          // 2048 tokens
#define LORA_SCALE 2.0f
#define EPSV 1e-6f

// ------------------------- scratch (device globals, no allocs) -------------------------
__device__ float g_x[MT*DIM];
__device__ float g_tx[MT*DIM];
__device__ float g_h[MT*DIM];
__device__ float g_th[MT*DIM];
__device__ float g_q[MT*DIM];
__device__ float g_dq[MT*DIM];
__device__ float g_k[MT*DIM];
__device__ float g_dk[MT*DIM];
__device__ float g_v[MT*DIM];
__device__ float g_dv[MT*DIM];
__device__ float g_o[MT*DIM];
__device__ float g_do[MT*DIM];
__device__ float g_u[MT*FFD];
__device__ float g_du[MT*FFD];
__device__ float g_p[(size_t)BSZ*NH*SEQ*SEQ];
__device__ float g_dp[(size_t)BSZ*NH*SEQ*SEQ];
__device__ float g_cp[MT*RNK];
__device__ float g_ct[MT*RNK];
__device__ float g_dAq[NL*RNK*DIM];
__device__ float g_dBq[NL*DIM*RNK];
__device__ float g_dAv[NL*RNK*DIM];
__device__ float g_dBv[NL*DIM*RNK];

// ------------------------- helpers -------------------------

__device__ __forceinline__ float to_tf32(float x) {
    uint32_t u;
    asm("cvt.rna.tf32.f32 %0, %1;" : "=r"(u) : "f"(x));
    return __uint_as_float(u);
}

__device__ __forceinline__ void mma_tf32(float c[4],
                                         uint32_t a0, uint32_t a1, uint32_t a2, uint32_t a3,
                                         uint32_t b0, uint32_t b1) {
    asm volatile(
        "mma.sync.aligned.m16n8k8.row.col.f32.tf32.tf32.f32 "
        "{%0,%1,%2,%3}, {%4,%5,%6,%7}, {%8,%9}, {%0,%1,%2,%3};\n"
        : "+f"(c[0]), "+f"(c[1]), "+f"(c[2]), "+f"(c[3])
        : "r"(a0), "r"(a1), "r"(a2), "r"(a3), "r"(b0), "r"(b1));
}

// ------------------------- kernels -------------------------

__global__ void k_embed(const int* __restrict__ ids, const float* __restrict__ emb,
                        float* __restrict__ x, float* __restrict__ tx)
{
    int i = blockIdx.x * 256 + threadIdx.x;          // MT*DIM total
    int tok = i >> 10;                                // DIM = 1024
    int d = i & 1023;
    x[i] = emb[(size_t)ids[tok] * DIM + d];
    tx[i] = 0.f;
}

__global__ void k_diff(const float* __restrict__ a, const float* __restrict__ b,
                       float* __restrict__ c, int n)
{
    int i = blockIdx.x * 256 + threadIdx.x;
    if (i < n) c[i] = a[i] - b[i];
}

// RMSNorm + JVP. One block per row (D=1024, 256 threads, 4 elems each).
// combine=1: H <- h + th (for the final layernorm, ALPHA=1 fused).
__global__ void k_rms(const float* __restrict__ X, const float* __restrict__ TX,
                      const float* __restrict__ g, float* __restrict__ H,
                      float* __restrict__ TH, int combine)
{
    const int row = blockIdx.x, tid = threadIdx.x;
    const float* x  = X  + (size_t)row * DIM;
    const float* tx = TX + (size_t)row * DIM;
    float xv[4], tv[4];
    float ss = 0.f, st = 0.f;
    #pragma unroll
    for (int e = 0; e < 4; e++) {
        int d = tid + e * 256;
        float a = x[d], b = tx[d];
        xv[e] = a; tv[e] = b;
        ss += a * a; st += a * b;
    }
    __shared__ float sa[8], sb[8];
    #pragma unroll
    for (int off = 16; off; off >>= 1) {
        ss += __shfl_down_sync(0xffffffffu, ss, off);
        st += __shfl_down_sync(0xffffffffu, st, off);
    }
    if ((tid & 31) == 0) { sa[tid >> 5] = ss; sb[tid >> 5] = st; }
    __syncthreads();
    if (tid < 32) {
        float a = (tid < 8) ? sa[tid] : 0.f;
        float b = (tid < 8) ? sb[tid] : 0.f;
        #pragma unroll
        for (int off = 4; off; off >>= 1) {
            a += __shfl_down_sync(0xffffffffu, a, off);
            b += __shfl_down_sync(0xffffffffu, b, off);
        }
        if (tid == 0) { sa[0] = a; sb[0] = b; }
    }
    __syncthreads();
    const float m  = sa[0] * (1.f / DIM);
    const float mm = sb[0] * (1.f / DIM);
    const float s  = 1.f / sqrtf(m + EPSV);
    const float s3mm = s * s * mm;
    #pragma unroll
    for (int e = 0; e < 4; e++) {
        int d = tid + e * 256;
        float gg = g[d];
        float hv  = gg * s * xv[e];
        float thv = gg * s * (tv[e] - xv[e] * s3mm);
        size_t idx = (size_t)row * DIM + d;
        if (combine) H[idx] = hv + thv;
        else { H[idx] = hv; TH[idx] = thv; }
    }
}

// Tensor-core tf32 GEMM: C[M,N] (+)= A[M,K] @ B[K,N], row-major.
// Block tile 128x128, K-tile 16, double-buffered smem.
// blockIdx.z selects (A1,C1) or (A2,C2) -> primal+tangent share B (L2 reuse).
// M % 128 == 0, N % 128 == 0, K % 16 == 0.
__global__ __launch_bounds__(256) void k_gemm_tc(
    const float* __restrict__ A1, const float* __restrict__ A2,
    const float* __restrict__ B,
    float* __restrict__ C1, float* __restrict__ C2,
    int M, int N, int K, int accum)
{
    const float* A = blockIdx.z ? A2 : A1;
    float* C = blockIdx.z ? C2 : C1;

    __shared__ float As[2][16][136];   // k-major, pad 8 -> bank = t*8+g (conflict-free frags)
    __shared__ float Bs[2][16][136];

    const int tid = threadIdx.x;
    const int wid = tid >> 5, lane = tid & 31;
    const int g = lane >> 2, t = lane & 3;
    const int wm = (wid >> 2) * 64;   // warp m-offset: 0 / 64
    const int wn = (wid & 3) * 32;    // warp n-offset: 0..96
    const int row0 = blockIdx.y * 128;
    const int col0 = blockIdx.x * 128;

    // per-thread global load coords
    const int a_r = tid >> 2, a_q = tid & 3;          // + e*64 rows
    const int b_k = tid >> 5, b_n = (tid & 31) * 4;   // + e*8 k-rows

    float acc[4][4][4];
    #pragma unroll
    for (int mi = 0; mi < 4; mi++)
        #pragma unroll
        for (int ni = 0; ni < 4; ni++)
            #pragma unroll
            for (int e = 0; e < 4; e++) acc[mi][ni][e] = 0.f;

    // prologue: load tile 0
    #pragma unroll
    for (int e = 0; e < 2; e++) {
        int r = a_r + e * 64;
        float4 va = *reinterpret_cast<const float4*>(&A[(size_t)(row0 + r) * K + a_q * 4]);
        As[0][a_q*4+0][r] = to_tf32(va.x); As[0][a_q*4+1][r] = to_tf32(va.y);
        As[0][a_q*4+2][r] = to_tf32(va.z); As[0][a_q*4+3][r] = to_tf32(va.w);
        int kr = b_k + e * 8;
        float4 vb = *reinterpret_cast<const float4*>(&B[(size_t)kr * N + col0 + b_n]);
        Bs[0][kr][b_n+0] = to_tf32(vb.x); Bs[0][kr][b_n+1] = to_tf32(vb.y);
        Bs[0][kr][b_n+2] = to_tf32(vb.z); Bs[0][kr][b_n+3] = to_tf32(vb.w);
    }
    __syncthreads();

    const int nkt = K >> 4;
    for (int kt = 0; kt < nkt; kt++) {
        const int cur = kt & 1;
        float4 pa[2], pb[2];
        const bool more = (kt + 1) < nkt;
        if (more) {
            int k0 = (kt + 1) * 16;
            #pragma unroll
            for (int e = 0; e < 2; e++) {
                pa[e] = *reinterpret_cast<const float4*>(
                    &A[(size_t)(row0 + a_r + e*64) * K + k0 + a_q * 4]);
                pb[e] = *reinterpret_cast<const float4*>(
                    &B[(size_t)(k0 + b_k + e*8) * N + col0 + b_n]);
            }
        }

        #pragma unroll
        for (int kk = 0; kk < 16; kk += 8) {
            uint32_t af[4][4], bf[4][2];
            #pragma unroll
            for (int mi = 0; mi < 4; mi++) {
                int r = wm + mi * 16 + g;
                af[mi][0] = __float_as_uint(As[cur][kk + t    ][r    ]);
                af[mi][1] = __float_as_uint(As[cur][kk + t    ][r + 8]);
                af[mi][2] = __float_as_uint(As[cur][kk + t + 4][r    ]);
                af[mi][3] = __float_as_uint(As[cur][kk + t + 4][r + 8]);
            }
            #pragma unroll
            for (int ni = 0; ni < 4; ni++) {
                int c = wn + ni * 8 + g;
                bf[ni][0] = __float_as_uint(Bs[cur][kk + t    ][c]);
                bf[ni][1] = __float_as_uint(Bs[cur][kk + t + 4][c]);
            }
            #pragma unroll
            for (int mi = 0; mi < 4; mi++)
                #pragma unroll
                for (int ni = 0; ni < 4; ni++)
                    mma_tf32(acc[mi][ni], af[mi][0], af[mi][1], af[mi][2], af[mi][3],
                             bf[ni][0], bf[ni][1]);
        }

        if (more) {
            const int nxt = cur ^ 1;
            #pragma unroll
            for (int e = 0; e < 2; e++) {
                int r = a_r + e * 64;
                As[nxt][a_q*4+0][r] = to_tf32(pa[e].x); As[nxt][a_q*4+1][r] = to_tf32(pa[e].y);
                As[nxt][a_q*4+2][r] = to_tf32(pa[e].z); As[nxt][a_q*4+3][r] = to_tf32(pa[e].w);
                int kr = b_k + e * 8;
                Bs[nxt][kr][b_n+0] = to_tf32(pb[e].x); Bs[nxt][kr][b_n+1] = to_tf32(pb[e].y);
                Bs[nxt][kr][b_n+2] = to_tf32(pb[e].z); Bs[nxt][kr][b_n+3] = to_tf32(pb[e].w);
            }
        }
        __syncthreads();
    }

    // epilogue
    #pragma unroll
    for (int mi = 0; mi < 4; mi++) {
        int r = row0 + wm + mi * 16 + g;
        #pragma unroll
        for (int ni = 0; ni < 4; ni++) {
            int c = col0 + wn + ni * 8 + 2 * t;
            size_t i0 = (size_t)r * N + c;
            size_t i1 = (size_t)(r + 8) * N + c;
            if (accum) {
                C[i0]     += acc[mi][ni][0];
                C[i0 + 1] += acc[mi][ni][1];
                C[i1]     += acc[mi][ni][2];
                C[i1 + 1] += acc[mi][ni][3];
            } else {
                C[i0]     = acc[mi][ni][0];
                C[i0 + 1] = acc[mi][ni][1];
                C[i1]     = acc[mi][ni][2];
                C[i1 + 1] = acc[mi][ni][3];
            }
        }
    }
}

// scores (NT, per head): out[bh,i,j] = scale * sum over pairs of A[.,i,:].B[.,j,:]
__global__ __launch_bounds__(256) void k_attn_nt(
    const float* __restrict__ Q1, const float* __restrict__ K1,
    const float* __restrict__ Q2, const float* __restrict__ K2,
    float* __restrict__ out, float scale, int dual)
{
    const int bh = blockIdx.z;
    const int b = bh >> 4, h = bh & 15;
    const int i0 = blockIdx.y * 64;
    const int j0 = blockIdx.x * 64;
    if (j0 > i0 + 63) return;       // fully masked -> never read
    __shared__ float Qs[64][65];
    __shared__ float Ks[64][65];
    const int tid = threadIdx.x;
    const int tx = tid & 15, ty = tid >> 4;
    const int hoff = h * 64;
    float acc[4][4];
    #pragma unroll
    for (int i = 0; i < 4; i++)
        #pragma unroll
        for (int j = 0; j < 4; j++) acc[i][j] = 0.f;

    for (int pass = 0; pass <= dual; ++pass) {
        const float* Q  = pass ? Q2 : Q1;
        const float* Kp = pass ? K2 : K1;
        #pragma unroll
        for (int e = 0; e < 4; e++) {
            int idx = tid + e * 256;          // 1024 float4 = 64x64
            int r = idx >> 4, c = (idx & 15) * 4;
            float4 vq = *reinterpret_cast<const float4*>(
                &Q[(size_t)(b * SEQ + i0 + r) * DIM + hoff + c]);
            Qs[r][c] = vq.x; Qs[r][c+1] = vq.y; Qs[r][c+2] = vq.z; Qs[r][c+3] = vq.w;
            float4 vk = *reinterpret_cast<const float4*>(
                &Kp[(size_t)(b * SEQ + j0 + r) * DIM + hoff + c]);
            Ks[r][c] = vk.x; Ks[r][c+1] = vk.y; Ks[r][c+2] = vk.z; Ks[r][c+3] = vk.w;
        }
        __syncthreads();
        #pragma unroll
        for (int kk = 0; kk < 64; kk++) {
            float a[4], bb[4];
            #pragma unroll
            for (int i = 0; i < 4; i++) a[i]  = Qs[ty * 4 + i][kk];
            #pragma unroll
            for (int j = 0; j < 4; j++) bb[j] = Ks[tx * 4 + j][kk];
            #pragma unroll
            for (int i = 0; i < 4; i++)
                #pragma unroll
                for (int j = 0; j < 4; j++)
                    acc[i][j] = fmaf(a[i], bb[j], acc[i][j]);
        }
        __syncthreads();
    }
    const size_t base = (size_t)bh * SEQ * SEQ;
    #pragma unroll
    for (int i = 0; i < 4; i++)
        #pragma unroll
        for (int j = 0; j < 4; j++)
            out[base + (size_t)(i0 + ty * 4 + i) * SEQ + j0 + tx * 4 + j] = acc[i][j] * scale;
}

// o (NN, per head): out[b,i,h,:] = sum over pairs of P[bh,i,:] @ V[b,:,h,:]
__global__ __launch_bounds__(256) void k_attn_nn(
    const float* __restrict__ P1, const float* __restrict__ V1,
    const float* __restrict__ P2, const float* __restrict__ V2,
    float* __restrict__ out, int dual)
{
    const int bh = blockIdx.z;
    const int b = bh >> 4, h = bh & 15;
    const int i0 = blockIdx.y * 64;
    __shared__ float Ps[64][65];
    __shared__ float Vs[64][65];
    const int tid = threadIdx.x;
    const int tx = tid & 15, ty = tid >> 4;
    const int hoff = h * 64;
    const int kend = i0 + 64;
    float acc[4][4];
    #pragma unroll
    for (int i = 0; i < 4; i++)
        #pragma unroll
        for (int j = 0; j < 4; j++) acc[i][j] = 0.f;

    const size_t pbase = (size_t)bh * SEQ * SEQ;
    for (int pass = 0; pass <= dual; ++pass) {
        const float* P = pass ? P2 : P1;
        const float* V = pass ? V2 : V1;
        for (int k0 = 0; k0 < kend; k0 += 64) {
            #pragma unroll
            for (int e = 0; e < 4; e++) {
                int idx = tid + e * 256;
                int r = idx >> 4, c = (idx & 15) * 4;
                float4 vp = *reinterpret_cast<const float4*>(
                    &P[pbase + (size_t)(i0 + r) * SEQ + k0 + c]);
                Ps[r][c] = vp.x; Ps[r][c+1] = vp.y; Ps[r][c+2] = vp.z; Ps[r][c+3] = vp.w;
                float4 vv = *reinterpret_cast<const float4*>(
                    &V[(size_t)(b * SEQ + k0 + r) * DIM + hoff + c]);
                Vs[r][c] = vv.x; Vs[r][c+1] = vv.y; Vs[r][c+2] = vv.z; Vs[r][c+3] = vv.w;
            }
            __syncthreads();
            #pragma unroll
            for (int kk = 0; kk < 64; kk++) {
                float a[4], bb[4];
                #pragma unroll
                for (int i = 0; i < 4; i++) a[i]  = Ps[ty * 4 + i][kk];
                #pragma unroll
                for (int j = 0; j < 4; j++) bb[j] = Vs[kk][tx * 4 + j];
                #pragma unroll
                for (int i = 0; i < 4; i++)
                    #pragma unroll
                    for (int j = 0; j < 4; j++)
                        acc[i][j] = fmaf(a[i], bb[j], acc[i][j]);
            }
            __syncthreads();
        }
    }
    #pragma unroll
    for (int i = 0; i < 4; i++)
        #pragma unroll
        for (int j = 0; j < 4; j++)
            out[(size_t)(b * SEQ + i0 + ty * 4 + i) * DIM + hoff + tx * 4 + j] = acc[i][j];
}

// Causal softmax + its JVP, in place. p <- softmax; ds <- p*(ds - <p,ds>).
__global__ void k_softmax(float* __restrict__ P, float* __restrict__ DS)
{
    const int i = blockIdx.x;
    const int bh = blockIdx.y;
    float* p  = P  + (size_t)bh * SEQ * SEQ + (size_t)i * SEQ;
    float* ds = DS + (size_t)bh * SEQ * SEQ + (size_t)i * SEQ;
    const int n = i + 1;
    const int tid = threadIdx.x;
    __shared__ float r0[8], r1[8], r2[8];

    float mx = -3.0e38f;
    for (int j = tid; j < n; j += 256) mx = fmaxf(mx, p[j]);
    #pragma unroll
    for (int off = 16; off; off >>= 1) mx = fmaxf(mx, __shfl_down_sync(0xffffffffu, mx, off));
    if ((tid & 31) == 0) r0[tid >> 5] = mx;
    __syncthreads();
    if (tid == 0) {
        float m = r0[0];
        for (int w = 1; w < 8; w++) m = fmaxf(m, r0[w]);
        r0[0] = m;
    }
    __syncthreads();
    const float m = r0[0];

    float s = 0.f, dt = 0.f;
    for (int j = tid; j < n; j += 256) {
        float e = expf(p[j] - m);
        p[j] = e;
        s += e;
        dt += e * ds[j];
    }
    #pragma unroll
    for (int off = 16; off; off >>= 1) {
        s  += __shfl_down_sync(0xffffffffu, s, off);
        dt += __shfl_down_sync(0xffffffffu, dt, off);
    }
    if ((tid & 31) == 0) { r1[tid >> 5] = s; r2[tid >> 5] = dt; }
    __syncthreads();
    if (tid == 0) {
        float a = 0.f, bq = 0.f;
        for (int w = 0; w < 8; w++) { a += r1[w]; bq += r2[w]; }
        r1[0] = a; r2[0] = bq;
    }
    __syncthreads();
    const float inv = 1.f / r1[0];
    const float pd = r2[0] * inv;
    for (int j = tid; j < SEQ; j += 256) {
        if (j < n) {
            float pv = p[j] * inv;
            p[j] = pv;
            ds[j] = pv * (ds[j] - pd);
        } else {
            p[j] = 0.f;
            ds[j] = 0.f;
        }
    }
}

// tanh-gelu + JVP, in place.
__global__ void k_gelu(float* __restrict__ U, float* __restrict__ DU)
{
    int i = blockIdx.x * 256 + threadIdx.x;
    float u = U[i], du = DU[i];
    float u2 = u * u;
    float w = 0.7978845608028654f * (u + 0.044715f * u * u2);
    float t = tanhf(w);
    float half1pt = 0.5f * (1.f + t);
    U[i] = u * half1pt;
    float dg = half1pt + 0.5f * u * (1.f - t * t) * 0.7978845608028654f * (1.f + 0.134145f * u2);
    DU[i] = du * dg;
}

// out[m,r] = X1[m,:].A1[r,:] (+ X2[m,:].A2[r,:])
__global__ void k_lora_down(const float* __restrict__ X1, const float* __restrict__ A1,
                            const float* __restrict__ X2, const float* __restrict__ A2,
                            float* __restrict__ out)
{
    __shared__ float xs[DIM];
    __shared__ float xs2[DIM];
    const int m = blockIdx.x, tid = threadIdx.x;
    #pragma unroll
    for (int e = 0; e < 4; e++) {
        int d = tid + e * 256;
        xs[d] = X1[(size_t)m * DIM + d];
        xs2[d] = X2 ? X2[(size_t)m * DIM + d] : 0.f;
    }
    __syncthreads();
    const int w = tid >> 5, lane = tid & 31;
    for (int r = w; r < RNK; r += 8) {
        float s = 0.f;
        const float* a1 = A1 + (size_t)r * DIM;
        for (int d = lane; d < DIM; d += 32) s += xs[d] * a1[d];
        if (X2) {
            const float* a2 = A2 + (size_t)r * DIM;
            for (int d = lane; d < DIM; d += 32) s += xs2[d] * a2[d];
        }
        #pragma unroll
        for (int off = 16; off; off >>= 1) s += __shfl_down_sync(0xffffffffu, s, off);
        if (lane == 0) out[m * RNK + r] = s;
    }
}

// C[m,d] += LORA_SCALE * ( C1[m,:].B1[d,:] (+ C2[m,:].B2[d,:]) ),  B* are [D,R]
__global__ void k_lora_up(float* __restrict__ C,
                          const float* __restrict__ C1, const float* __restrict__ B1,
                          const float* __restrict__ C2, const float* __restrict__ B2)
{
    const int m = blockIdx.y;
    const int d = blockIdx.x * 256 + threadIdx.x;
    __shared__ float c1[RNK], c2[RNK];
    if (threadIdx.x < RNK) {
        c1[threadIdx.x] = C1[m * RNK + threadIdx.x];
        c2[threadIdx.x] = C2 ? C2[m * RNK + threadIdx.x] : 0.f;
    }
    __syncthreads();
    float s = 0.f;
    const float* b1 = B1 + (size_t)d * RNK;
    #pragma unroll
    for (int r = 0; r < RNK; r++) s += c1[r] * b1[r];
    if (C2) {
        const float* b2 = B2 + (size_t)d * RNK;
        #pragma unroll
        for (int r = 0; r < RNK; r++) s += c2[r] * b2[r];
    }
    C[(size_t)m * DIM + d] += LORA_SCALE * s;
}

// ------------------------- host -------------------------

extern "C" void kernel_launch(void* const* d_in, const int* in_sizes, int n_in,
                              void* d_out, int out_size)
{
    (void)in_sizes; (void)n_in; (void)out_size;
    const int*   ids  = (const int*)  d_in[0];
    const float* emb  = (const float*)d_in[1];
    const float* Wq   = (const float*)d_in[2];
    const float* Wk   = (const float*)d_in[3];
    const float* Wv   = (const float*)d_in[4];
    const float* Wo   = (const float*)d_in[5];
    const float* W1   = (const float*)d_in[6];
    const float* W2   = (const float*)d_in[7];
    const float* ln1  = (const float*)d_in[8];
    const float* ln2  = (const float*)d_in[9];
    const float* lnf  = (const float*)d_in[10];
    const float* lm   = (const float*)d_in[11];
    const float* Aq0  = (const float*)d_in[12];
    const float* Bq0  = (const float*)d_in[13];
    const float* Av0  = (const float*)d_in[14];
    const float* Bv0  = (const float*)d_in[15];
    const float* Aq   = (const float*)d_in[16];
    const float* Bq   = (const float*)d_in[17];
    const float* Av   = (const float*)d_in[18];
    const float* Bv   = (const float*)d_in[19];
    float* out = (float*)d_out;

    float *x, *tx, *h, *th, *q, *dq, *k, *dk, *v, *dv, *o, *dO, *u, *du, *P, *DP;
    float *cp, *ct, *dAq, *dBq, *dAv, *dBv;
    cudaGetSymbolAddress((void**)&x,  g_x);
    cudaGetSymbolAddress((void**)&tx, g_tx);
    cudaGetSymbolAddress((void**)&h,  g_h);
    cudaGetSymbolAddress((void**)&th, g_th);
    cudaGetSymbolAddress((void**)&q,  g_q);
    cudaGetSymbolAddress((void**)&dq, g_dq);
    cudaGetSymbolAddress((void**)&k,  g_k);
    cudaGetSymbolAddress((void**)&dk, g_dk);
    cudaGetSymbolAddress((void**)&v,  g_v);
    cudaGetSymbolAddress((void**)&dv, g_dv);
    cudaGetSymbolAddress((void**)&o,  g_o);
    cudaGetSymbolAddress((void**)&dO, g_do);
    cudaGetSymbolAddress((void**)&u,  g_u);
    cudaGetSymbolAddress((void**)&du, g_du);
    cudaGetSymbolAddress((void**)&P,  g_p);
    cudaGetSymbolAddress((void**)&DP, g_dp);
    cudaGetSymbolAddress((void**)&cp, g_cp);
    cudaGetSymbolAddress((void**)&ct, g_ct);
    cudaGetSymbolAddress((void**)&dAq, g_dAq);
    cudaGetSymbolAddress((void**)&dBq, g_dBq);
    cudaGetSymbolAddress((void**)&dAv, g_dAv);
    cudaGetSymbolAddress((void**)&dBv, g_dBv);

    k_embed<<<MT*DIM/256, 256>>>(ids, emb, x, tx);
    k_diff<<<(NL*RNK*DIM+255)/256, 256>>>(Aq, Aq0, dAq, NL*RNK*DIM);
    k_diff<<<(NL*DIM*RNK+255)/256, 256>>>(Bq, Bq0, dBq, NL*DIM*RNK);
    k_diff<<<(NL*RNK*DIM+255)/256, 256>>>(Av, Av0, dAv, NL*RNK*DIM);
    k_diff<<<(NL*DIM*RNK+255)/256, 256>>>(Bv, Bv0, dBv, NL*DIM*RNK);

    const dim3 gD2(DIM/128, MT/128, 2);   // paired (primal+tangent) N=1024 GEMMs
    const dim3 gF2(FFD/128, MT/128, 2);   // paired N=4096 GEMMs
    const dim3 gV1(VOC/128, MT/128, 1);   // lm_head
    const dim3 gNT(SEQ/64, SEQ/64, BSZ*NH);
    const dim3 gNN(1, SEQ/64, BSZ*NH);
    const dim3 gLU(DIM/256, MT);

    for (int l = 0; l < NL; l++) {
        const float* wq  = Wq + (size_t)l*DIM*DIM;
        const float* wk  = Wk + (size_t)l*DIM*DIM;
        const float* wv  = Wv + (size_t)l*DIM*DIM;
        const float* wo  = Wo + (size_t)l*DIM*DIM;
        const float* w1  = W1 + (size_t)l*DIM*FFD;
        const float* w2  = W2 + (size_t)l*FFD*DIM;
        const float* aq0 = Aq0 + (size_t)l*RNK*DIM;
        const float* bq0 = Bq0 + (size_t)l*DIM*RNK;
        const float* av0 = Av0 + (size_t)l*RNK*DIM;
        const float* bv0 = Bv0 + (size_t)l*DIM*RNK;
        const float* daq = dAq + (size_t)l*RNK*DIM;
        const float* dbq = dBq + (size_t)l*DIM*RNK;
        const float* dav = dAv + (size_t)l*RNK*DIM;
        const float* dbv = dBv + (size_t)l*DIM*RNK;

        // pre-attn RMSNorm (primal h, tangent th)
        k_rms<<<MT, 256>>>(x, tx, ln1 + l*DIM, h, th, 0);

        // q/dq, k/dk, v/dv via tensor-core GEMMs (paired: share B in L2)
        k_gemm_tc<<<gD2, 256>>>(h, th, wq, q, dq, MT, DIM, DIM, 0);
        k_gemm_tc<<<gD2, 256>>>(h, th, wk, k, dk, MT, DIM, DIM, 0);
        k_gemm_tc<<<gD2, 256>>>(h, th, wv, v, dv, MT, DIM, DIM, 0);

        // LoRA corrections on q/dq
        k_lora_down<<<MT, 256>>>(h,  aq0, nullptr, nullptr, cp);
        k_lora_down<<<MT, 256>>>(th, aq0, h, daq, ct);
        k_lora_up<<<gLU, 256>>>(q,  cp, bq0, nullptr, nullptr);
        k_lora_up<<<gLU, 256>>>(dq, ct, bq0, cp, dbq);

        // LoRA corrections on v/dv
        k_lora_down<<<MT, 256>>>(h,  av0, nullptr, nullptr, cp);
        k_lora_down<<<MT, 256>>>(th, av0, h, dav, ct);
        k_lora_up<<<gLU, 256>>>(v,  cp, bv0, nullptr, nullptr);
        k_lora_up<<<gLU, 256>>>(dv, ct, bv0, cp, dbv);

        // attention scores + JVP
        k_attn_nt<<<gNT, 256>>>(q,  k, nullptr, nullptr, P,  0.125f, 0);
        k_attn_nt<<<gNT, 256>>>(dq, k, q,       dk,      DP, 0.125f, 1);
        k_softmax<<<dim3(SEQ, BSZ*NH), 256>>>(P, DP);
        k_attn_nn<<<gNN, 256>>>(P,  v, nullptr, nullptr, o,  0);
        k_attn_nn<<<gNN, 256>>>(DP, v, P,       dv,      dO, 1);

        // residual: x += o@Wo, tx += do@Wo
        k_gemm_tc<<<gD2, 256>>>(o, dO, wo, x, tx, MT, DIM, DIM, 1);

        // FFN
        k_rms<<<MT, 256>>>(x, tx, ln2 + l*DIM, h, th, 0);
        k_gemm_tc<<<gF2, 256>>>(h, th, w1, u, du, MT, FFD, DIM, 0);
        k_gelu<<<MT*FFD/256, 256>>>(u, du);
        k_gemm_tc<<<gD2, 256>>>(u, du, w2, x, tx, MT, DIM, FFD, 1);
    }

    // final norm: z = rms(x) + rms_jvp(x,tx)  (ALPHA=1), then lm_head
    k_rms<<<MT, 256>>>(x, tx, lnf, h, nullptr, 1);
    k_gemm_tc<<<gV1, 256>>>(h, nullptr, lm, out, nullptr, MT, VOC, DIM, 0);
}